// round 13
// baseline (speedup 1.0000x reference)
#include <cuda_runtime.h>
#include <math.h>

// Problem constants
#define BB 2
#define LL 2048
#define EE 1024
#define HH 16
#define DD 64
#define MM (BB*LL)    // 4096 rows
#define BH (BB*HH)    // 32 batch*heads

#define PSTR 20       // proj smem stride (16 k-words + 4 pad)
#define FSTR 68       // fused smem stride for 64-wide K dim
#define FVSTR 72      // V smem stride (conflict-free scalar b-frags)

// Scratch in head-split layout [B,H,L,D]
__device__ float g_q[BH*LL*DD];
__device__ float g_k[BH*LL*DD];
__device__ float g_v[BH*LL*DD];
__device__ float g_z[BH*LL*DD];

// ---------------------------------------------------------------------------
// helpers
// ---------------------------------------------------------------------------
__device__ __forceinline__ unsigned f2t(float x) {
    unsigned u;
    asm("cvt.rna.tf32.f32 %0, %1;" : "=r"(u) : "f"(x));
    return u;
}

__device__ __forceinline__ void mma8(float* c, const unsigned* a, const unsigned* b) {
    asm volatile(
        "mma.sync.aligned.m16n8k8.row.col.f32.tf32.tf32.f32 "
        "{%0,%1,%2,%3}, {%4,%5,%6,%7}, {%8,%9}, {%0,%1,%2,%3};\n"
        : "+f"(c[0]), "+f"(c[1]), "+f"(c[2]), "+f"(c[3])
        : "r"(a[0]), "r"(a[1]), "r"(a[2]), "r"(a[3]), "r"(b[0]), "r"(b[1]));
}

__device__ __forceinline__ void ldsm4(unsigned* r, unsigned saddr) {
    asm volatile("ldmatrix.sync.aligned.m8n8.x4.shared.b16 {%0,%1,%2,%3}, [%4];"
                 : "=r"(r[0]), "=r"(r[1]), "=r"(r[2]), "=r"(r[3]) : "r"(saddr));
}

// A-frag lane address (16 rows x 8 k-words)
__device__ __forceinline__ unsigned a_addr(unsigned sbase, int r0, int k0, int S, int lane) {
    int row = r0 + (lane & 15);
    int kw  = k0 + ((lane >> 4) << 2);
    return sbase + (unsigned)(row * S + kw) * 4u;
}
// B-frag lane address (16 cols x 8 k-words -> two n-tiles)
__device__ __forceinline__ unsigned b_addr(unsigned sbase, int c0, int k0, int S, int lane) {
    int col = c0 + (lane & 7) + ((lane >> 4) << 3);
    int kw  = k0 + (((lane >> 3) & 1) << 2);
    return sbase + (unsigned)(col * S + kw) * 4u;
}

// ---------------------------------------------------------------------------
// proj3: all three projections in one launch (blockIdx.z selects).
// Block 128x128, K-step 16, 8 warps (4m x 2n), warp tile 32x64.
// ---------------------------------------------------------------------------
__global__ __launch_bounds__(256) void proj3_mma(
        const float* __restrict__ query, const float* __restrict__ key,
        const float* __restrict__ value,
        const float* __restrict__ Wq, const float* __restrict__ bq,
        const float* __restrict__ Wk, const float* __restrict__ bk,
        const float* __restrict__ Wv, const float* __restrict__ bv,
        float* __restrict__ qh, float* __restrict__ kh, float* __restrict__ vh) {
    __shared__ unsigned As[128 * PSTR];
    __shared__ unsigned Bs[128 * PSTR];
    const unsigned sA = (unsigned)__cvta_generic_to_shared(As);
    const unsigned sB = (unsigned)__cvta_generic_to_shared(Bs);

    const float *X, *W, *bias;
    float* outh;
    if (blockIdx.z == 0)      { X = query; W = Wq; bias = bq; outh = qh; }
    else if (blockIdx.z == 1) { X = key;   W = Wk; bias = bk; outh = kh; }
    else                      { X = value; W = Wv; bias = bv; outh = vh; }

    const int m0 = blockIdx.y * 128, n0 = blockIdx.x * 128;
    const int tid = threadIdx.x, wid = tid >> 5, lane = tid & 31;
    const int qr = lane >> 2, qc = lane & 3;
    const int wm = (wid & 3) * 32, wn = (wid >> 2) * 64;
    float acc[2][8][4] = {};

    for (int kb = 0; kb < EE; kb += 16) {
#pragma unroll
        for (int i = 0; i < 2; i++) {
            int idx = tid + i * 256;
            int rr = idx >> 2, c4 = idx & 3;
            float4 xv = *(const float4*)&X[(size_t)(m0 + rr) * EE + kb + c4 * 4];
            *(uint4*)&As[rr * PSTR + c4 * 4] =
                make_uint4(f2t(xv.x), f2t(xv.y), f2t(xv.z), f2t(xv.w));
            float4 wv = *(const float4*)&W[(size_t)(n0 + rr) * EE + kb + c4 * 4];
            *(uint4*)&Bs[rr * PSTR + c4 * 4] =
                make_uint4(f2t(wv.x), f2t(wv.y), f2t(wv.z), f2t(wv.w));
        }
        __syncthreads();
#pragma unroll
        for (int ks = 0; ks < 16; ks += 8) {
            unsigned a[2][4], b[4][4];
            ldsm4(a[0], a_addr(sA, wm, ks, PSTR, lane));
            ldsm4(a[1], a_addr(sA, wm + 16, ks, PSTR, lane));
#pragma unroll
            for (int g = 0; g < 4; g++)
                ldsm4(b[g], b_addr(sB, wn + g * 16, ks, PSTR, lane));
#pragma unroll
            for (int mt = 0; mt < 2; mt++)
#pragma unroll
                for (int nt = 0; nt < 8; nt++) {
                    unsigned bb[2] = { b[nt >> 1][(nt & 1) * 2], b[nt >> 1][(nt & 1) * 2 + 1] };
                    mma8(acc[mt][nt], a[mt], bb);
                }
        }
        __syncthreads();
    }

#pragma unroll
    for (int mt = 0; mt < 2; mt++) {
        int m = m0 + wm + mt * 16 + qr;
        int b = m >> 11, l = m & (LL - 1);
#pragma unroll
        for (int nt = 0; nt < 8; nt++) {
            int e = wn + n0 + nt * 8 + 2 * qc;
            int h = e >> 6, dd = e & 63;
            size_t base = ((size_t)(b * HH + h) * LL + l) * DD + dd;
            *(float2*)&outh[base] =
                make_float2(acc[mt][nt][0] + bias[e], acc[mt][nt][1] + bias[e + 1]);
            *(float2*)&outh[base + 8 * (size_t)DD] =
                make_float2(acc[mt][nt][2] + bias[e], acc[mt][nt][3] + bias[e + 1]);
        }
    }
}

// ---------------------------------------------------------------------------
// Fused attention: scores + softmax + PV, two-sweep (R3 verbatim).
// Dynamic smem: QP (Q then P, 128xFSTR) | Ks (64xFSTR) | Vs (64xFVSTR)
// ---------------------------------------------------------------------------
#define SM_QP 0
#define SM_K  (128*FSTR)                 // 8704
#define SM_V  (SM_K + 64*FSTR)           // 13056
#define SM_TOT_WORDS (SM_V + 64*FVSTR)   // 17664 words = 70656 B

__global__ __launch_bounds__(256) void fused_attn(float* __restrict__ wts) {
    extern __shared__ unsigned sm[];
    unsigned* QP = sm + SM_QP;
    unsigned* Ks = sm + SM_K;
    unsigned* Vs = sm + SM_V;
    const unsigned sQP = (unsigned)__cvta_generic_to_shared(QP);
    const unsigned sK  = (unsigned)__cvta_generic_to_shared(Ks);

    const int bh = blockIdx.y;
    const int m0 = blockIdx.x * 128;
    const float* __restrict__ Q  = g_q + (size_t)bh * LL * DD;
    const float* __restrict__ Kg = g_k + (size_t)bh * LL * DD;
    const float* __restrict__ Vg = g_v + (size_t)bh * LL * DD;
    const int tid = threadIdx.x, w = tid >> 5, lane = tid & 31;
    const int qr = lane >> 2, qc = lane & 3;
    const float cs = 0.125f;

    // ---- load Q tile ----
#pragma unroll
    for (int i = 0; i < 8; i++) {
        int idx = tid + i * 256;
        int r = idx >> 4, c4 = idx & 15;
        float4 v = *(const float4*)&Q[(size_t)(m0 + r) * DD + c4 * 4];
        *(uint4*)&QP[r * FSTR + c4 * 4] = make_uint4(f2t(v.x), f2t(v.y), f2t(v.z), f2t(v.w));
    }
    __syncthreads();

    // ---- Q fragments into registers (held whole kernel) ----
    unsigned aq[8][4];
#pragma unroll
    for (int ks = 0; ks < 8; ks++)
        ldsm4(aq[ks], a_addr(sQP, w * 16, ks * 8, FSTR, lane));

    float mrun[2] = { -1e30f, -1e30f };
    float srun[2] = { 0.f, 0.f };

    // ================= sweep 1: row max & sum =================
    for (int nt = 0; nt < 32; nt++) {
        __syncthreads();
#pragma unroll
        for (int i = 0; i < 4; i++) {
            int idx = tid + i * 256;
            int r = idx >> 4, c4 = idx & 15;
            float4 v = *(const float4*)&Kg[(size_t)(nt * 64 + r) * DD + c4 * 4];
            *(uint4*)&Ks[r * FSTR + c4 * 4] = make_uint4(f2t(v.x), f2t(v.y), f2t(v.z), f2t(v.w));
        }
        __syncthreads();

        float sc[8][4] = {};
#pragma unroll
        for (int ks = 0; ks < 8; ks++) {
            unsigned b[4][4];
#pragma unroll
            for (int g = 0; g < 4; g++)
                ldsm4(b[g], b_addr(sK, g * 16, ks * 8, FSTR, lane));
#pragma unroll
            for (int j = 0; j < 8; j++) {
                unsigned bb[2] = { b[j >> 1][(j & 1) * 2], b[j >> 1][(j & 1) * 2 + 1] };
                mma8(sc[j], aq[ks], bb);
            }
        }
#pragma unroll
        for (int t = 0; t < 2; t++) {
            float tm = -1e30f;
#pragma unroll
            for (int j = 0; j < 8; j++)
                tm = fmaxf(tm, fmaxf(sc[j][2 * t], sc[j][2 * t + 1]));
            tm = fmaxf(tm, __shfl_xor_sync(0xffffffffu, tm, 1));
            tm = fmaxf(tm, __shfl_xor_sync(0xffffffffu, tm, 2));
            tm *= cs;
            float mn = fmaxf(mrun[t], tm);
            float ps = 0.f;
#pragma unroll
            for (int j = 0; j < 8; j++) {
                ps += __expf(fmaf(sc[j][2 * t], cs, -mn));
                ps += __expf(fmaf(sc[j][2 * t + 1], cs, -mn));
            }
            ps += __shfl_xor_sync(0xffffffffu, ps, 1);
            ps += __shfl_xor_sync(0xffffffffu, ps, 2);
            srun[t] = srun[t] * __expf(mrun[t] - mn) + ps;
            mrun[t] = mn;
        }
    }
    const float inv_s[2] = { 1.f / srun[0], 1.f / srun[1] };

    // ================= sweep 2: recompute, write weights, PV =================
    float zc[8][4] = {};
    float* __restrict__ Wr = wts + (size_t)bh * LL * LL;

    for (int nt = 0; nt < 32; nt++) {
        __syncthreads();
#pragma unroll
        for (int i = 0; i < 4; i++) {
            int idx = tid + i * 256;
            int r = idx >> 4, c4 = idx & 15;
            float4 v = *(const float4*)&Kg[(size_t)(nt * 64 + r) * DD + c4 * 4];
            *(uint4*)&Ks[r * FSTR + c4 * 4] = make_uint4(f2t(v.x), f2t(v.y), f2t(v.z), f2t(v.w));
            float4 u = *(const float4*)&Vg[(size_t)(nt * 64 + r) * DD + c4 * 4];
            *(uint4*)&Vs[r * FVSTR + c4 * 4] = make_uint4(f2t(u.x), f2t(u.y), f2t(u.z), f2t(u.w));
        }
        __syncthreads();

        float sc[8][4] = {};
#pragma unroll
        for (int ks = 0; ks < 8; ks++) {
            unsigned b[4][4];
#pragma unroll
            for (int g = 0; g < 4; g++)
                ldsm4(b[g], b_addr(sK, g * 16, ks * 8, FSTR, lane));
#pragma unroll
            for (int j = 0; j < 8; j++) {
                unsigned bb[2] = { b[j >> 1][(j & 1) * 2], b[j >> 1][(j & 1) * 2 + 1] };
                mma8(sc[j], aq[ks], bb);
            }
        }

        // probabilities: write to gmem weights + stage tf32 into QP (as P)
        const int mrow = m0 + w * 16 + qr;
#pragma unroll
        for (int j = 0; j < 8; j++) {
            int colb = nt * 64 + j * 8 + 2 * qc;
            float p0 = __expf(fmaf(sc[j][0], cs, -mrun[0])) * inv_s[0];
            float p1 = __expf(fmaf(sc[j][1], cs, -mrun[0])) * inv_s[0];
            float p2 = __expf(fmaf(sc[j][2], cs, -mrun[1])) * inv_s[1];
            float p3 = __expf(fmaf(sc[j][3], cs, -mrun[1])) * inv_s[1];
            *(float2*)&Wr[(size_t)mrow * LL + colb] = make_float2(p0, p1);
            *(float2*)&Wr[(size_t)(mrow + 8) * LL + colb] = make_float2(p2, p3);
            *(uint2*)&QP[(w * 16 + qr) * FSTR + j * 8 + 2 * qc] = make_uint2(f2t(p0), f2t(p1));
            *(uint2*)&QP[(w * 16 + qr + 8) * FSTR + j * 8 + 2 * qc] = make_uint2(f2t(p2), f2t(p3));
        }
        __syncwarp();

        // PV: A = P rows (warp-private), B = V (scalar frags from Vs)
#pragma unroll
        for (int ks = 0; ks < 8; ks++) {
            unsigned ap[4];
            ldsm4(ap, a_addr(sQP, w * 16, ks * 8, FSTR, lane));
#pragma unroll
            for (int j = 0; j < 8; j++) {
                unsigned bb[2];
                bb[0] = Vs[(ks * 8 + qc) * FVSTR + j * 8 + qr];
                bb[1] = Vs[(ks * 8 + 4 + qc) * FVSTR + j * 8 + qr];
                mma8(zc[j], ap, bb);
            }
        }
    }

    // ---- write Z ----
    const int mrow = m0 + w * 16 + qr;
#pragma unroll
    for (int j = 0; j < 8; j++) {
        int d = j * 8 + 2 * qc;
        *(float2*)&g_z[((size_t)bh * LL + mrow) * DD + d] = make_float2(zc[j][0], zc[j][1]);
        *(float2*)&g_z[((size_t)bh * LL + mrow + 8) * DD + d] = make_float2(zc[j][2], zc[j][3]);
    }
}

// ---------------------------------------------------------------------------
// out: out[m,e] = Zrow[m,:]·Wo[e,:] + bo[e]. Z in head layout.
// ---------------------------------------------------------------------------
__global__ __launch_bounds__(256) void out_mma(const float* __restrict__ Wo,
                                               const float* __restrict__ bo,
                                               float* __restrict__ out) {
    __shared__ unsigned As[128 * PSTR];
    __shared__ unsigned Bs[128 * PSTR];
    const unsigned sA = (unsigned)__cvta_generic_to_shared(As);
    const unsigned sB = (unsigned)__cvta_generic_to_shared(Bs);
    const int m0 = blockIdx.y * 128, n0 = blockIdx.x * 128;
    const int tid = threadIdx.x, wid = tid >> 5, lane = tid & 31;
    const int qr = lane >> 2, qc = lane & 3;
    const int wm = (wid & 3) * 32, wn = (wid >> 2) * 64;
    float acc[2][8][4] = {};

    for (int kb = 0; kb < EE; kb += 16) {
        const int h = kb >> 6;
        const int dbase = kb & 63;
#pragma unroll
        for (int i = 0; i < 2; i++) {
            int idx = tid + i * 256;
            int rr = idx >> 2, c4 = idx & 3;
            int m = m0 + rr;
            int b = m >> 11, l = m & (LL - 1);
            float4 xv = *(const float4*)&g_z[((size_t)(b * HH + h) * LL + l) * DD + dbase + c4 * 4];
            *(uint4*)&As[rr * PSTR + c4 * 4] =
                make_uint4(f2t(xv.x), f2t(xv.y), f2t(xv.z), f2t(xv.w));
            float4 wv = *(const float4*)&Wo[(size_t)(n0 + rr) * EE + kb + c4 * 4];
            *(uint4*)&Bs[rr * PSTR + c4 * 4] =
                make_uint4(f2t(wv.x), f2t(wv.y), f2t(wv.z), f2t(wv.w));
        }
        __syncthreads();
#pragma unroll
        for (int ks = 0; ks < 16; ks += 8) {
            unsigned a[2][4], b[4][4];
            ldsm4(a[0], a_addr(sA, wm, ks, PSTR, lane));
            ldsm4(a[1], a_addr(sA, wm + 16, ks, PSTR, lane));
#pragma unroll
            for (int g = 0; g < 4; g++)
                ldsm4(b[g], b_addr(sB, wn + g * 16, ks, PSTR, lane));
#pragma unroll
            for (int mt = 0; mt < 2; mt++)
#pragma unroll
                for (int nt = 0; nt < 8; nt++) {
                    unsigned bb[2] = { b[nt >> 1][(nt & 1) * 2], b[nt >> 1][(nt & 1) * 2 + 1] };
                    mma8(acc[mt][nt], a[mt], bb);
                }
        }
        __syncthreads();
    }

#pragma unroll
    for (int mt = 0; mt < 2; mt++) {
        int m = m0 + wm + mt * 16 + qr;
#pragma unroll
        for (int nt = 0; nt < 8; nt++) {
            int e = n0 + wn + nt * 8 + 2 * qc;
            size_t base = (size_t)m * EE + e;
            *(float2*)&out[base] =
                make_float2(acc[mt][nt][0] + bo[e], acc[mt][nt][1] + bo[e + 1]);
            *(float2*)&out[base + 8 * (size_t)EE] =
                make_float2(acc[mt][nt][2] + bo[e], acc[mt][nt][3] + bo[e + 1]);
        }
    }
}

// ---------------------------------------------------------------------------
extern "C" void kernel_launch(void* const* d_in, const int* in_sizes, int n_in,
                              void* d_out, int out_size) {
    const float* query = (const float*)d_in[0];
    const float* key   = (const float*)d_in[1];
    const float* value = (const float*)d_in[2];
    const float* Wq    = (const float*)d_in[3];
    const float* bq    = (const float*)d_in[4];
    const float* Wk    = (const float*)d_in[5];
    const float* bk    = (const float*)d_in[6];
    const float* Wv    = (const float*)d_in[7];
    const float* bv    = (const float*)d_in[8];
    const float* Wo    = (const float*)d_in[9];
    const float* bo    = (const float*)d_in[10];

    float* out = (float*)d_out;
    float* wts = out + (size_t)MM * EE;   // tuple order: (out, weights)

    float *qh, *kh, *vh;
    cudaGetSymbolAddress((void**)&qh, g_q);
    cudaGetSymbolAddress((void**)&kh, g_k);
    cudaGetSymbolAddress((void**)&vh, g_v);

    cudaFuncSetAttribute(fused_attn, cudaFuncAttributeMaxDynamicSharedMemorySize,
                         SM_TOT_WORDS * 4);

    dim3 blk(256);
    dim3 gproj(EE / 128, MM / 128, 3);       // 8 x 32 x 3
    proj3_mma<<<gproj, blk>>>(query, key, value, Wq, bq, Wk, bk, Wv, bv, qh, kh, vh);

    dim3 gf(LL / 128, BH);                   // 16 x 32
    fused_attn<<<gf, blk, SM_TOT_WORDS * 4>>>(wts);

    dim3 gout(EE / 128, MM / 128);           // 8 x 32
    out_mma<<<gout, blk>>>(Wo, bo, out);
}

// round 14
// speedup vs baseline: 1.0067x; 1.0067x over previous
#include <cuda_runtime.h>
#include <math.h>

// Problem constants
#define BB 2
#define LL 2048
#define EE 1024
#define HH 16
#define DD 64
#define MM (BB*LL)    // 4096 rows
#define BH (BB*HH)    // 32 batch*heads

#define PSTR 20       // proj smem stride (16 k-words + 4 pad)
#define FSTR 68       // fused smem stride for 64-wide K dim
#define FVSTR 72      // V smem stride (conflict-free scalar b-frags)

// Scratch in head-split layout [B,H,L,D]
__device__ float g_q[BH*LL*DD];
__device__ float g_k[BH*LL*DD];
__device__ float g_v[BH*LL*DD];
__device__ float g_z[BH*LL*DD];

// ---------------------------------------------------------------------------
// helpers
// ---------------------------------------------------------------------------
__device__ __forceinline__ unsigned f2t(float x) {
    unsigned u;
    asm("cvt.rna.tf32.f32 %0, %1;" : "=r"(u) : "f"(x));
    return u;
}

__device__ __forceinline__ void mma8(float* c, const unsigned* a, const unsigned* b) {
    asm volatile(
        "mma.sync.aligned.m16n8k8.row.col.f32.tf32.tf32.f32 "
        "{%0,%1,%2,%3}, {%4,%5,%6,%7}, {%8,%9}, {%0,%1,%2,%3};\n"
        : "+f"(c[0]), "+f"(c[1]), "+f"(c[2]), "+f"(c[3])
        : "r"(a[0]), "r"(a[1]), "r"(a[2]), "r"(a[3]), "r"(b[0]), "r"(b[1]));
}

__device__ __forceinline__ void ldsm4(unsigned* r, unsigned saddr) {
    asm volatile("ldmatrix.sync.aligned.m8n8.x4.shared.b16 {%0,%1,%2,%3}, [%4];"
                 : "=r"(r[0]), "=r"(r[1]), "=r"(r[2]), "=r"(r[3]) : "r"(saddr));
}

// A-frag lane address (16 rows x 8 k-words)
__device__ __forceinline__ unsigned a_addr(unsigned sbase, int r0, int k0, int S, int lane) {
    int row = r0 + (lane & 15);
    int kw  = k0 + ((lane >> 4) << 2);
    return sbase + (unsigned)(row * S + kw) * 4u;
}
// B-frag lane address (16 cols x 8 k-words -> two n-tiles)
__device__ __forceinline__ unsigned b_addr(unsigned sbase, int c0, int k0, int S, int lane) {
    int col = c0 + (lane & 7) + ((lane >> 4) << 3);
    int kw  = k0 + (((lane >> 3) & 1) << 2);
    return sbase + (unsigned)(col * S + kw) * 4u;
}

// ---------------------------------------------------------------------------
// proj3: all three projections in one launch (blockIdx.z selects).
// Block 128x128, K-step 16, 8 warps (4m x 2n), warp tile 32x64.
// ---------------------------------------------------------------------------
__global__ __launch_bounds__(256) void proj3_mma(
        const float* __restrict__ query, const float* __restrict__ key,
        const float* __restrict__ value,
        const float* __restrict__ Wq, const float* __restrict__ bq,
        const float* __restrict__ Wk, const float* __restrict__ bk,
        const float* __restrict__ Wv, const float* __restrict__ bv,
        float* __restrict__ qh, float* __restrict__ kh, float* __restrict__ vh) {
    __shared__ unsigned As[128 * PSTR];
    __shared__ unsigned Bs[128 * PSTR];
    const unsigned sA = (unsigned)__cvta_generic_to_shared(As);
    const unsigned sB = (unsigned)__cvta_generic_to_shared(Bs);

    const float *X, *W, *bias;
    float* outh;
    if (blockIdx.z == 0)      { X = query; W = Wq; bias = bq; outh = qh; }
    else if (blockIdx.z == 1) { X = key;   W = Wk; bias = bk; outh = kh; }
    else                      { X = value; W = Wv; bias = bv; outh = vh; }

    const int m0 = blockIdx.y * 128, n0 = blockIdx.x * 128;
    const int tid = threadIdx.x, wid = tid >> 5, lane = tid & 31;
    const int qr = lane >> 2, qc = lane & 3;
    const int wm = (wid & 3) * 32, wn = (wid >> 2) * 64;
    float acc[2][8][4] = {};

    for (int kb = 0; kb < EE; kb += 16) {
#pragma unroll
        for (int i = 0; i < 2; i++) {
            int idx = tid + i * 256;
            int rr = idx >> 2, c4 = idx & 3;
            float4 xv = *(const float4*)&X[(size_t)(m0 + rr) * EE + kb + c4 * 4];
            *(uint4*)&As[rr * PSTR + c4 * 4] =
                make_uint4(f2t(xv.x), f2t(xv.y), f2t(xv.z), f2t(xv.w));
            float4 wv = *(const float4*)&W[(size_t)(n0 + rr) * EE + kb + c4 * 4];
            *(uint4*)&Bs[rr * PSTR + c4 * 4] =
                make_uint4(f2t(wv.x), f2t(wv.y), f2t(wv.z), f2t(wv.w));
        }
        __syncthreads();
#pragma unroll
        for (int ks = 0; ks < 16; ks += 8) {
            unsigned a[2][4], b[4][4];
            ldsm4(a[0], a_addr(sA, wm, ks, PSTR, lane));
            ldsm4(a[1], a_addr(sA, wm + 16, ks, PSTR, lane));
#pragma unroll
            for (int g = 0; g < 4; g++)
                ldsm4(b[g], b_addr(sB, wn + g * 16, ks, PSTR, lane));
#pragma unroll
            for (int mt = 0; mt < 2; mt++)
#pragma unroll
                for (int nt = 0; nt < 8; nt++) {
                    unsigned bb[2] = { b[nt >> 1][(nt & 1) * 2], b[nt >> 1][(nt & 1) * 2 + 1] };
                    mma8(acc[mt][nt], a[mt], bb);
                }
        }
        __syncthreads();
    }

#pragma unroll
    for (int mt = 0; mt < 2; mt++) {
        int m = m0 + wm + mt * 16 + qr;
        int b = m >> 11, l = m & (LL - 1);
#pragma unroll
        for (int nt = 0; nt < 8; nt++) {
            int e = wn + n0 + nt * 8 + 2 * qc;
            int h = e >> 6, dd = e & 63;
            size_t base = ((size_t)(b * HH + h) * LL + l) * DD + dd;
            *(float2*)&outh[base] =
                make_float2(acc[mt][nt][0] + bias[e], acc[mt][nt][1] + bias[e + 1]);
            *(float2*)&outh[base + 8 * (size_t)DD] =
                make_float2(acc[mt][nt][2] + bias[e], acc[mt][nt][3] + bias[e + 1]);
        }
    }
}

// ---------------------------------------------------------------------------
// Fused attention: scores + softmax + PV, two-sweep (R3 verbatim).
// Dynamic smem: QP (Q then P, 128xFSTR) | Ks (64xFSTR) | Vs (64xFVSTR)
// ---------------------------------------------------------------------------
#define SM_QP 0
#define SM_K  (128*FSTR)                 // 8704
#define SM_V  (SM_K + 64*FSTR)           // 13056
#define SM_TOT_WORDS (SM_V + 64*FVSTR)   // 17664 words = 70656 B

__global__ __launch_bounds__(256) void fused_attn(float* __restrict__ wts) {
    extern __shared__ unsigned sm[];
    unsigned* QP = sm + SM_QP;
    unsigned* Ks = sm + SM_K;
    unsigned* Vs = sm + SM_V;
    const unsigned sQP = (unsigned)__cvta_generic_to_shared(QP);
    const unsigned sK  = (unsigned)__cvta_generic_to_shared(Ks);

    const int bh = blockIdx.y;
    const int m0 = blockIdx.x * 128;
    const float* __restrict__ Q  = g_q + (size_t)bh * LL * DD;
    const float* __restrict__ Kg = g_k + (size_t)bh * LL * DD;
    const float* __restrict__ Vg = g_v + (size_t)bh * LL * DD;
    const int tid = threadIdx.x, w = tid >> 5, lane = tid & 31;
    const int qr = lane >> 2, qc = lane & 3;
    const float cs = 0.125f;

    // ---- load Q tile ----
#pragma unroll
    for (int i = 0; i < 8; i++) {
        int idx = tid + i * 256;
        int r = idx >> 4, c4 = idx & 15;
        float4 v = *(const float4*)&Q[(size_t)(m0 + r) * DD + c4 * 4];
        *(uint4*)&QP[r * FSTR + c4 * 4] = make_uint4(f2t(v.x), f2t(v.y), f2t(v.z), f2t(v.w));
    }
    __syncthreads();

    // ---- Q fragments into registers (held whole kernel) ----
    unsigned aq[8][4];
#pragma unroll
    for (int ks = 0; ks < 8; ks++)
        ldsm4(aq[ks], a_addr(sQP, w * 16, ks * 8, FSTR, lane));

    float mrun[2] = { -1e30f, -1e30f };
    float srun[2] = { 0.f, 0.f };

    // ================= sweep 1: row max & sum =================
    for (int nt = 0; nt < 32; nt++) {
        __syncthreads();
#pragma unroll
        for (int i = 0; i < 4; i++) {
            int idx = tid + i * 256;
            int r = idx >> 4, c4 = idx & 15;
            float4 v = *(const float4*)&Kg[(size_t)(nt * 64 + r) * DD + c4 * 4];
            *(uint4*)&Ks[r * FSTR + c4 * 4] = make_uint4(f2t(v.x), f2t(v.y), f2t(v.z), f2t(v.w));
        }
        __syncthreads();

        float sc[8][4] = {};
#pragma unroll
        for (int ks = 0; ks < 8; ks++) {
            unsigned b[4][4];
#pragma unroll
            for (int g = 0; g < 4; g++)
                ldsm4(b[g], b_addr(sK, g * 16, ks * 8, FSTR, lane));
#pragma unroll
            for (int j = 0; j < 8; j++) {
                unsigned bb[2] = { b[j >> 1][(j & 1) * 2], b[j >> 1][(j & 1) * 2 + 1] };
                mma8(sc[j], aq[ks], bb);
            }
        }
#pragma unroll
        for (int t = 0; t < 2; t++) {
            float tm = -1e30f;
#pragma unroll
            for (int j = 0; j < 8; j++)
                tm = fmaxf(tm, fmaxf(sc[j][2 * t], sc[j][2 * t + 1]));
            tm = fmaxf(tm, __shfl_xor_sync(0xffffffffu, tm, 1));
            tm = fmaxf(tm, __shfl_xor_sync(0xffffffffu, tm, 2));
            tm *= cs;
            float mn = fmaxf(mrun[t], tm);
            float ps = 0.f;
#pragma unroll
            for (int j = 0; j < 8; j++) {
                ps += __expf(fmaf(sc[j][2 * t], cs, -mn));
                ps += __expf(fmaf(sc[j][2 * t + 1], cs, -mn));
            }
            ps += __shfl_xor_sync(0xffffffffu, ps, 1);
            ps += __shfl_xor_sync(0xffffffffu, ps, 2);
            srun[t] = srun[t] * __expf(mrun[t] - mn) + ps;
            mrun[t] = mn;
        }
    }
    const float inv_s[2] = { 1.f / srun[0], 1.f / srun[1] };

    // ================= sweep 2: recompute, write weights, PV =================
    float zc[8][4] = {};
    float* __restrict__ Wr = wts + (size_t)bh * LL * LL;

    for (int nt = 0; nt < 32; nt++) {
        __syncthreads();
#pragma unroll
        for (int i = 0; i < 4; i++) {
            int idx = tid + i * 256;
            int r = idx >> 4, c4 = idx & 15;
            float4 v = *(const float4*)&Kg[(size_t)(nt * 64 + r) * DD + c4 * 4];
            *(uint4*)&Ks[r * FSTR + c4 * 4] = make_uint4(f2t(v.x), f2t(v.y), f2t(v.z), f2t(v.w));
            float4 u = *(const float4*)&Vg[(size_t)(nt * 64 + r) * DD + c4 * 4];
            *(uint4*)&Vs[r * FVSTR + c4 * 4] = make_uint4(f2t(u.x), f2t(u.y), f2t(u.z), f2t(u.w));
        }
        __syncthreads();

        float sc[8][4] = {};
#pragma unroll
        for (int ks = 0; ks < 8; ks++) {
            unsigned b[4][4];
#pragma unroll
            for (int g = 0; g < 4; g++)
                ldsm4(b[g], b_addr(sK, g * 16, ks * 8, FSTR, lane));
#pragma unroll
            for (int j = 0; j < 8; j++) {
                unsigned bb[2] = { b[j >> 1][(j & 1) * 2], b[j >> 1][(j & 1) * 2 + 1] };
                mma8(sc[j], aq[ks], bb);
            }
        }

        // probabilities: write to gmem weights + stage tf32 into QP (as P)
        const int mrow = m0 + w * 16 + qr;
#pragma unroll
        for (int j = 0; j < 8; j++) {
            int colb = nt * 64 + j * 8 + 2 * qc;
            float p0 = __expf(fmaf(sc[j][0], cs, -mrun[0])) * inv_s[0];
            float p1 = __expf(fmaf(sc[j][1], cs, -mrun[0])) * inv_s[0];
            float p2 = __expf(fmaf(sc[j][2], cs, -mrun[1])) * inv_s[1];
            float p3 = __expf(fmaf(sc[j][3], cs, -mrun[1])) * inv_s[1];
            *(float2*)&Wr[(size_t)mrow * LL + colb] = make_float2(p0, p1);
            *(float2*)&Wr[(size_t)(mrow + 8) * LL + colb] = make_float2(p2, p3);
            *(uint2*)&QP[(w * 16 + qr) * FSTR + j * 8 + 2 * qc] = make_uint2(f2t(p0), f2t(p1));
            *(uint2*)&QP[(w * 16 + qr + 8) * FSTR + j * 8 + 2 * qc] = make_uint2(f2t(p2), f2t(p3));
        }
        __syncwarp();

        // PV: A = P rows (warp-private), B = V (scalar frags from Vs)
#pragma unroll
        for (int ks = 0; ks < 8; ks++) {
            unsigned ap[4];
            ldsm4(ap, a_addr(sQP, w * 16, ks * 8, FSTR, lane));
#pragma unroll
            for (int j = 0; j < 8; j++) {
                unsigned bb[2];
                bb[0] = Vs[(ks * 8 + qc) * FVSTR + j * 8 + qr];
                bb[1] = Vs[(ks * 8 + 4 + qc) * FVSTR + j * 8 + qr];
                mma8(zc[j], ap, bb);
            }
        }
    }

    // ---- write Z ----
    const int mrow = m0 + w * 16 + qr;
#pragma unroll
    for (int j = 0; j < 8; j++) {
        int d = j * 8 + 2 * qc;
        *(float2*)&g_z[((size_t)bh * LL + mrow) * DD + d] = make_float2(zc[j][0], zc[j][1]);
        *(float2*)&g_z[((size_t)bh * LL + mrow + 8) * DD + d] = make_float2(zc[j][2], zc[j][3]);
    }
}

// ---------------------------------------------------------------------------
// out: out[m,e] = Zrow[m,:]·Wo[e,:] + bo[e]. Z in head layout.
// ---------------------------------------------------------------------------
__global__ __launch_bounds__(256) void out_mma(const float* __restrict__ Wo,
                                               const float* __restrict__ bo,
                                               float* __restrict__ out) {
    __shared__ unsigned As[128 * PSTR];
    __shared__ unsigned Bs[128 * PSTR];
    const unsigned sA = (unsigned)__cvta_generic_to_shared(As);
    const unsigned sB = (unsigned)__cvta_generic_to_shared(Bs);
    const int m0 = blockIdx.y * 128, n0 = blockIdx.x * 128;
    const int tid = threadIdx.x, wid = tid >> 5, lane = tid & 31;
    const int qr = lane >> 2, qc = lane & 3;
    const int wm = (wid & 3) * 32, wn = (wid >> 2) * 64;
    float acc[2][8][4] = {};

    for (int kb = 0; kb < EE; kb += 16) {
        const int h = kb >> 6;
        const int dbase = kb & 63;
#pragma unroll
        for (int i = 0; i < 2; i++) {
            int idx = tid + i * 256;
            int rr = idx >> 2, c4 = idx & 3;
            int m = m0 + rr;
            int b = m >> 11, l = m & (LL - 1);
            float4 xv = *(const float4*)&g_z[((size_t)(b * HH + h) * LL + l) * DD + dbase + c4 * 4];
            *(uint4*)&As[rr * PSTR + c4 * 4] =
                make_uint4(f2t(xv.x), f2t(xv.y), f2t(xv.z), f2t(xv.w));
            float4 wv = *(const float4*)&Wo[(size_t)(n0 + rr) * EE + kb + c4 * 4];
            *(uint4*)&Bs[rr * PSTR + c4 * 4] =
                make_uint4(f2t(wv.x), f2t(wv.y), f2t(wv.z), f2t(wv.w));
        }
        __syncthreads();
#pragma unroll
        for (int ks = 0; ks < 16; ks += 8) {
            unsigned a[2][4], b[4][4];
            ldsm4(a[0], a_addr(sA, wm, ks, PSTR, lane));
            ldsm4(a[1], a_addr(sA, wm + 16, ks, PSTR, lane));
#pragma unroll
            for (int g = 0; g < 4; g++)
                ldsm4(b[g], b_addr(sB, wn + g * 16, ks, PSTR, lane));
#pragma unroll
            for (int mt = 0; mt < 2; mt++)
#pragma unroll
                for (int nt = 0; nt < 8; nt++) {
                    unsigned bb[2] = { b[nt >> 1][(nt & 1) * 2], b[nt >> 1][(nt & 1) * 2 + 1] };
                    mma8(acc[mt][nt], a[mt], bb);
                }
        }
        __syncthreads();
    }

#pragma unroll
    for (int mt = 0; mt < 2; mt++) {
        int m = m0 + wm + mt * 16 + qr;
#pragma unroll
        for (int nt = 0; nt < 8; nt++) {
            int e = n0 + wn + nt * 8 + 2 * qc;
            size_t base = (size_t)m * EE + e;
            *(float2*)&out[base] =
                make_float2(acc[mt][nt][0] + bo[e], acc[mt][nt][1] + bo[e + 1]);
            *(float2*)&out[base + 8 * (size_t)EE] =
                make_float2(acc[mt][nt][2] + bo[e], acc[mt][nt][3] + bo[e + 1]);
        }
    }
}

// ---------------------------------------------------------------------------
extern "C" void kernel_launch(void* const* d_in, const int* in_sizes, int n_in,
                              void* d_out, int out_size) {
    const float* query = (const float*)d_in[0];
    const float* key   = (const float*)d_in[1];
    const float* value = (const float*)d_in[2];
    const float* Wq    = (const float*)d_in[3];
    const float* bq    = (const float*)d_in[4];
    const float* Wk    = (const float*)d_in[5];
    const float* bk    = (const float*)d_in[6];
    const float* Wv    = (const float*)d_in[7];
    const float* bv    = (const float*)d_in[8];
    const float* Wo    = (const float*)d_in[9];
    const float* bo    = (const float*)d_in[10];

    float* out = (float*)d_out;
    float* wts = out + (size_t)MM * EE;   // tuple order: (out, weights)

    float *qh, *kh, *vh;
    cudaGetSymbolAddress((void**)&qh, g_q);
    cudaGetSymbolAddress((void**)&kh, g_k);
    cudaGetSymbolAddress((void**)&vh, g_v);

    cudaFuncSetAttribute(fused_attn, cudaFuncAttributeMaxDynamicSharedMemorySize,
                         SM_TOT_WORDS * 4);

    dim3 blk(256);
    dim3 gproj(EE / 128, MM / 128, 3);       // 8 x 32 x 3
    proj3_mma<<<gproj, blk>>>(query, key, value, Wq, bq, Wk, bk, Wv, bv, qh, kh, vh);

    dim3 gf(LL / 128, BH);                   // 16 x 32
    fused_attn<<<gf, blk, SM_TOT_WORDS * 4>>>(wts);

    dim3 gout(EE / 128, MM / 128);           // 8 x 32
    out_mma<<<gout, blk>>>(Wo, bo, out);
}